// round 4
// baseline (speedup 1.0000x reference)
#include <cuda_runtime.h>
#include <cuda_bf16.h>

#define N_NODES 100000

// Scratch: __device__ globals (zero-init at load; every kernel self-cleans so
// the state at entry of each call — correctness run, capture, replay — is
// identical: deg=0, wacc=0, p=0, S=0).
__device__ float  g_deg [N_NODES];
__device__ float  g_dinv[N_NODES];
__device__ float4 g_y   [N_NODES];   // x * dinv (pre-scaled source features)
__device__ float  g_wacc[N_NODES];   // per-src sum of dinv[dst]
__device__ float4 g_p   [N_NODES];   // sum of y[src] per dst (dinv[dst] deferred)
__device__ float  g_S   [64];        // sum_s w[s] * relu(p_s @ W1 + b1)

// K1: in-degree count (dst half only), 2 edges/thread.
__global__ void k_deg(const int2* __restrict__ dst2, int E2) {
    int t = blockIdx.x * blockDim.x + threadIdx.x;
    if (t >= E2) return;
    int2 d = dst2[t];
    if ((unsigned)d.x < (unsigned)N_NODES) atomicAdd(&g_deg[d.x], 1.0f);
    if ((unsigned)d.y < (unsigned)N_NODES) atomicAdd(&g_deg[d.y], 1.0f);
}

// K2: dinv = rsqrt(deg+1) (self loop), y = x*dinv. Resets deg for next replay.
__global__ void k_prep(const float4* __restrict__ x) {
    int i = blockIdx.x * blockDim.x + threadIdx.x;
    if (i >= N_NODES) return;
    float di = rsqrtf(g_deg[i] + 1.0f);
    g_deg[i]  = 0.0f;                 // self-clean
    g_dinv[i] = di;
    float4 xv = x[i];
    g_y[i] = make_float4(xv.x * di, xv.y * di, xv.z * di, xv.w * di);
}

// K3: fused edge pass, 2 edges/thread. 4 random L2 ops per edge:
//   p[dst]   += y[src]        (RED.v4, payload straight from the gather)
//   wacc[src] += dinv[dst]    (RED scalar)
__global__ void k_edge(const int2* __restrict__ src2,
                       const int2* __restrict__ dst2,
                       int E2) {
    int t = blockIdx.x * blockDim.x + threadIdx.x;
    if (t >= E2) return;
    int2 s = src2[t];
    int2 d = dst2[t];
    bool ok0 = (unsigned)s.x < (unsigned)N_NODES && (unsigned)d.x < (unsigned)N_NODES;
    bool ok1 = (unsigned)s.y < (unsigned)N_NODES && (unsigned)d.y < (unsigned)N_NODES;
    float4 y0, y1;
    float nd0 = 0.f, nd1 = 0.f;
    if (ok0) { y0 = __ldg(&g_y[s.x]); nd0 = __ldg(&g_dinv[d.x]); }
    if (ok1) { y1 = __ldg(&g_y[s.y]); nd1 = __ldg(&g_dinv[d.y]); }
    if (ok0) {
        asm volatile("red.global.add.v4.f32 [%0], {%1, %2, %3, %4};"
                     :: "l"((float*)&g_p[d.x]),
                        "f"(y0.x), "f"(y0.y), "f"(y0.z), "f"(y0.w) : "memory");
        atomicAdd(&g_wacc[s.x], nd0);
    }
    if (ok1) {
        asm volatile("red.global.add.v4.f32 [%0], {%1, %2, %3, %4};"
                     :: "l"((float*)&g_p[d.y]),
                        "f"(y1.x), "f"(y1.y), "f"(y1.z), "f"(y1.w) : "memory");
        atomicAdd(&g_wacc[s.y], nd1);
    }
}

// K4: node pass.
//   pfull = dinv[i] * (p[i] + y[i])          (deferred dst scale + self loop)
//   a     = relu(pfull @ W1 + b1)            (4 -> 64)
//   w     = dinv[i]*(dinv[i] + wacc[i])
//   S    += w * a
// tid&63 = column j, tid>>6 = node subgroup (4 nodes per block-iter).
// Self-cleans p and wacc (sync between read and reset — 64 threads share i).
__global__ void k_node(const float* __restrict__ W1,
                       const float* __restrict__ b1) {
    int j = threadIdx.x & 63;
    int g = threadIdx.x >> 6;              // 0..3
    float w0 = W1[j], w1 = W1[64 + j], w2 = W1[128 + j], w3 = W1[192 + j];
    float bb = b1[j];
    float acc = 0.f;
    for (int i = blockIdx.x * 4 + g; i < N_NODES; i += gridDim.x * 4) {
        float di   = g_dinv[i];
        float4 pa  = g_p[i];
        float4 yv  = g_y[i];
        float wa   = g_wacc[i];
        __syncthreads();               // all 64 sharers finished reading i
        if (j == 0) {                  // self-clean for next replay
            g_p[i] = make_float4(0.f, 0.f, 0.f, 0.f);
            g_wacc[i] = 0.0f;
        }
        float p0 = di * (pa.x + yv.x);
        float p1 = di * (pa.y + yv.y);
        float p2 = di * (pa.z + yv.z);
        float p3 = di * (pa.w + yv.w);
        float a = fmaf(p0, w0, fmaf(p1, w1, fmaf(p2, w2, fmaf(p3, w3, bb))));
        a = fmaxf(a, 0.f);
        float wn = di * (di + wa);
        acc = fmaf(wn, a, acc);
    }
    __shared__ float sh[256];
    sh[threadIdx.x] = acc;
    __syncthreads();
    if (threadIdx.x < 64) {
        float s = sh[threadIdx.x] + sh[threadIdx.x + 64]
                + sh[threadIdx.x + 128] + sh[threadIdx.x + 192];
        atomicAdd(&g_S[threadIdx.x], s);
    }
}

// K5: out[k] = (S @ W2)[k] / n + b2[k]. Self-cleans S.
__global__ void k_final(const float* __restrict__ W2,
                        const float* __restrict__ b2,
                        float* __restrict__ out) {
    __shared__ float sS[64];
    int t = threadIdx.x;               // 0..63
    sS[t] = g_S[t];
    __syncthreads();
    g_S[t] = 0.0f;                     // self-clean
    if (t < 32) {
        float s = 0.f;
        #pragma unroll
        for (int j = 0; j < 64; j++) s = fmaf(sS[j], W2[j * 32 + t], s);
        out[t] = s * (1.0f / (float)N_NODES) + b2[t];
    }
}

extern "C" void kernel_launch(void* const* d_in, const int* in_sizes, int n_in,
                              void* d_out, int out_size) {
    const float4* x  = (const float4*)d_in[0];   // [100000, 4] f32
    const int*    ei = (const int*)d_in[1];      // [2, E] int32
    const float*  W1 = (const float*)d_in[2];    // [4, 64]
    const float*  b1 = (const float*)d_in[3];    // [64]
    const float*  W2 = (const float*)d_in[4];    // [64, 32]
    const float*  b2 = (const float*)d_in[5];    // [32]
    float*        out = (float*)d_out;           // [32]

    int E  = in_sizes[1] / 2;
    int E2 = E / 2;                              // E is even (3.2M)
    const int2* src2 = (const int2*)ei;
    const int2* dst2 = (const int2*)(ei + E);

    const int T = 256;
    int nb_nodes  = (N_NODES + T - 1) / T;
    int nb_edges2 = (E2 + T - 1) / T;

    k_deg  <<<nb_edges2, T>>>(dst2, E2);
    k_prep <<<nb_nodes, T>>>(x);
    k_edge <<<nb_edges2, T>>>(src2, dst2, E2);
    k_node <<<1024, T>>>(W1, b1);
    k_final<<<1, 64>>>(W2, b2, out);
}

// round 5
// speedup vs baseline: 1.1621x; 1.1621x over previous
#include <cuda_runtime.h>
#include <cuda_bf16.h>

#define N_NODES 100000

// Scratch: __device__ globals (zero-init at load). Replay invariant: at entry
// of every call, deg=0 (k_prep cleaned it last call); p/wacc/S are cleaned by
// k_deg itself before k_edge/k_node consume them.
__device__ float  g_deg [N_NODES];
__device__ float  g_dinv[N_NODES];
__device__ float4 g_y   [N_NODES];   // x * dinv (pre-scaled source features)
__device__ float  g_wacc[N_NODES];   // per-src sum of dinv[dst]
__device__ float4 g_p   [N_NODES];   // sum of y[src] per dst (dinv[dst] deferred)
__device__ float  g_S   [64];        // sum_s w[s] * relu(p_s @ W1 + b1)

// K1: in-degree count (dst half only), 2 edges/thread. Also zeroes p/wacc/S
// (streaming stores, no hazard — those arrays are only read by later kernels).
__global__ void k_deg(const int2* __restrict__ dst2, int E2) {
    int t = blockIdx.x * blockDim.x + threadIdx.x;
    if (t < N_NODES) {
        g_p[t]    = make_float4(0.f, 0.f, 0.f, 0.f);
        g_wacc[t] = 0.0f;
    }
    if (t < 64) g_S[t] = 0.0f;
    if (t >= E2) return;
    int2 d = dst2[t];
    if ((unsigned)d.x < (unsigned)N_NODES) atomicAdd(&g_deg[d.x], 1.0f);
    if ((unsigned)d.y < (unsigned)N_NODES) atomicAdd(&g_deg[d.y], 1.0f);
}

// K2: dinv = rsqrt(deg+1) (self loop), y = x*dinv. Resets deg for next replay.
__global__ void k_prep(const float4* __restrict__ x) {
    int i = blockIdx.x * blockDim.x + threadIdx.x;
    if (i >= N_NODES) return;
    float di = rsqrtf(g_deg[i] + 1.0f);
    g_deg[i]  = 0.0f;                 // self-clean (free: line already owned)
    g_dinv[i] = di;
    float4 xv = x[i];
    g_y[i] = make_float4(xv.x * di, xv.y * di, xv.z * di, xv.w * di);
}

// K3: fused edge pass, 2 edges/thread. 4 random L2 ops per edge:
//   p[dst]   += y[src]        (RED.v4, payload straight from the gather)
//   wacc[src] += dinv[dst]    (RED scalar)
__global__ void k_edge(const int2* __restrict__ src2,
                       const int2* __restrict__ dst2,
                       int E2) {
    int t = blockIdx.x * blockDim.x + threadIdx.x;
    if (t >= E2) return;
    int2 s = src2[t];
    int2 d = dst2[t];
    bool ok0 = (unsigned)s.x < (unsigned)N_NODES && (unsigned)d.x < (unsigned)N_NODES;
    bool ok1 = (unsigned)s.y < (unsigned)N_NODES && (unsigned)d.y < (unsigned)N_NODES;
    float4 y0, y1;
    float nd0 = 0.f, nd1 = 0.f;
    if (ok0) { y0 = __ldg(&g_y[s.x]); nd0 = __ldg(&g_dinv[d.x]); }
    if (ok1) { y1 = __ldg(&g_y[s.y]); nd1 = __ldg(&g_dinv[d.y]); }
    if (ok0) {
        asm volatile("red.global.add.v4.f32 [%0], {%1, %2, %3, %4};"
                     :: "l"((float*)&g_p[d.x]),
                        "f"(y0.x), "f"(y0.y), "f"(y0.z), "f"(y0.w) : "memory");
        atomicAdd(&g_wacc[s.x], nd0);
    }
    if (ok1) {
        asm volatile("red.global.add.v4.f32 [%0], {%1, %2, %3, %4};"
                     :: "l"((float*)&g_p[d.y]),
                        "f"(y1.x), "f"(y1.y), "f"(y1.z), "f"(y1.w) : "memory");
        atomicAdd(&g_wacc[s.y], nd1);
    }
}

// K4: node pass (pure read, no barriers in loop).
//   pfull = dinv[i] * (p[i] + y[i])          (deferred dst scale + self loop)
//   a     = relu(pfull @ W1 + b1)            (4 -> 64)
//   w     = dinv[i]*(dinv[i] + wacc[i])
//   S    += w * a
// tid&63 = column j, tid>>6 = node subgroup (4 nodes per block-iter).
__global__ void k_node(const float* __restrict__ W1,
                       const float* __restrict__ b1) {
    int j = threadIdx.x & 63;
    int g = threadIdx.x >> 6;              // 0..3
    float w0 = W1[j], w1 = W1[64 + j], w2 = W1[128 + j], w3 = W1[192 + j];
    float bb = b1[j];
    float acc = 0.f;
    for (int i = blockIdx.x * 4 + g; i < N_NODES; i += gridDim.x * 4) {
        float di   = g_dinv[i];
        float4 pa  = g_p[i];
        float4 yv  = g_y[i];
        float wa   = g_wacc[i];
        float p0 = di * (pa.x + yv.x);
        float p1 = di * (pa.y + yv.y);
        float p2 = di * (pa.z + yv.z);
        float p3 = di * (pa.w + yv.w);
        float a = fmaf(p0, w0, fmaf(p1, w1, fmaf(p2, w2, fmaf(p3, w3, bb))));
        a = fmaxf(a, 0.f);
        float wn = di * (di + wa);
        acc = fmaf(wn, a, acc);
    }
    __shared__ float sh[256];
    sh[threadIdx.x] = acc;
    __syncthreads();
    if (threadIdx.x < 64) {
        float s = sh[threadIdx.x] + sh[threadIdx.x + 64]
                + sh[threadIdx.x + 128] + sh[threadIdx.x + 192];
        atomicAdd(&g_S[threadIdx.x], s);
    }
}

// K5: out[k] = (S @ W2)[k] / n + b2[k].  (S is re-zeroed by next call's k_deg)
__global__ void k_final(const float* __restrict__ W2,
                        const float* __restrict__ b2,
                        float* __restrict__ out) {
    __shared__ float sS[64];
    int t = threadIdx.x;               // 0..63
    sS[t] = g_S[t];
    __syncthreads();
    if (t < 32) {
        float s = 0.f;
        #pragma unroll
        for (int j = 0; j < 64; j++) s = fmaf(sS[j], W2[j * 32 + t], s);
        out[t] = s * (1.0f / (float)N_NODES) + b2[t];
    }
}

extern "C" void kernel_launch(void* const* d_in, const int* in_sizes, int n_in,
                              void* d_out, int out_size) {
    const float4* x  = (const float4*)d_in[0];   // [100000, 4] f32
    const int*    ei = (const int*)d_in[1];      // [2, E] int32
    const float*  W1 = (const float*)d_in[2];    // [4, 64]
    const float*  b1 = (const float*)d_in[3];    // [64]
    const float*  W2 = (const float*)d_in[4];    // [64, 32]
    const float*  b2 = (const float*)d_in[5];    // [32]
    float*        out = (float*)d_out;           // [32]

    int E  = in_sizes[1] / 2;
    int E2 = E / 2;                              // E is even (3.2M)
    const int2* src2 = (const int2*)ei;
    const int2* dst2 = (const int2*)(ei + E);

    const int T = 256;
    int nb_nodes  = (N_NODES + T - 1) / T;
    int nb_edges2 = (E2 + T - 1) / T;

    k_deg  <<<nb_edges2, T>>>(dst2, E2);
    k_prep <<<nb_nodes, T>>>(x);
    k_edge <<<nb_edges2, T>>>(src2, dst2, E2);
    k_node <<<1024, T>>>(W1, b1);
    k_final<<<1, 64>>>(W2, b2, out);
}